// round 8
// baseline (speedup 1.0000x reference)
#include <cuda_runtime.h>
#include <cuda_bf16.h>
#include <math.h>

#define H_DIM 1000
#define W_DIM 1000
#define NVERT 20
#define PX 4
#define BLOCK 256                  // 250 active threads cover one row
#define ROWS_PB 4
#define GRID (H_DIM / ROWS_PB)     // 250 blocks

__global__ void __launch_bounds__(256)
render_kernel(const float* __restrict__ vpos,
              const float* __restrict__ vcol,
              const float* __restrict__ vrad,
              const float* __restrict__ cpos,
              const float* __restrict__ crot,
              const float* __restrict__ fl,
              const float* __restrict__ bg,
              float* __restrict__ out)
{
    const int tid  = threadIdx.x;
    const int lane = tid & 31;
    const int row0 = blockIdx.x * ROWS_PB;

    // ---- per-warp register prepass, done ONCE for all ROWS_PB rows ----
    const int vi = (lane < NVERT) ? lane : 0;
    float px_ = vpos[3*vi+0], py_ = vpos[3*vi+1], pz_ = vpos[3*vi+2];
    float x = fmaf(px_, crot[0], fmaf(py_, crot[3], fmaf(pz_, crot[6], cpos[0])));
    float y = fmaf(px_, crot[1], fmaf(py_, crot[4], fmaf(pz_, crot[7], cpos[1])));
    float z = fmaf(px_, crot[2], fmaf(py_, crot[5], fmaf(pz_, crot[8], cpos[2])));
    float f    = fl[0];
    float invz = __fdividef(1.0f, z);
    float xn = f * x * invz;
    float yn = f * y * invz;
    float rn = f * vrad[vi] * invz;
    float r2v = rn * rn;
    bool in_depth = (z > 1.0f) && (z < 45.0f);
    float closeness = fminf(fmaxf((45.0f - z) * (1.0f / 44.0f), 0.0f), 1.0f);
    float Ev  = in_depth ? __expf(closeness * 10.0f) : 0.0f;   // bg logit 0 -> e^0 = 1
    float Ecr = Ev * vcol[3*vi+0];
    float Ecg = Ev * vcol[3*vi+1];
    float Ecb = Ev * vcol[3*vi+2];
    bool live = (lane < NVERT) && (Ev > 0.0f);

    const float bgr = bg[0], bgg = bg[1], bgb = bg[2];

    const float dgx = -2.0f / W_DIM;
    const int   x0  = tid * PX;
    const float gx0 = 1.0f - (2.0f * x0 + 1.0f) * (1.0f / W_DIM);

#pragma unroll
    for (int rr = 0; rr < ROWS_PB; rr++) {
        const int row = row0 + rr;
        const float gy = 1.0f - (2.0f * row + 1.0f) * (1.0f / H_DIM);

        // per-row coverage vote (cheap: 4 instr + ballot)
        float dyv = gy - yn;
        unsigned mask = __ballot_sync(0xffffffffu, live && (dyv * dyv <= r2v));

        float s0 = 1.0f, s1 = 1.0f, s2 = 1.0f, s3 = 1.0f;
        float r0 = bgr, g0 = bgg, b0 = bgb;
        float r1 = bgr, g1 = bgg, b1 = bgb;
        float r2_ = bgr, g2 = bgg, b2 = bgb;
        float r3 = bgr, g3 = bgg, b3 = bgb;

        while (mask) {
            int i = __ffs(mask) - 1;
            mask &= mask - 1;
            float axn = __shfl_sync(0xffffffffu, xn,  i);
            float ayn = __shfl_sync(0xffffffffu, yn,  i);
            float ar2 = __shfl_sync(0xffffffffu, r2v, i);
            float aE  = __shfl_sync(0xffffffffu, Ev,  i);
            float acr = __shfl_sync(0xffffffffu, Ecr, i);
            float acg = __shfl_sync(0xffffffffu, Ecg, i);
            float acb = __shfl_sync(0xffffffffu, Ecb, i);

            float dy  = gy - ayn;
            float dy2 = dy * dy;

            float dx0 = gx0 - axn;
            float d0  = fmaf(dx0, dx0, dy2);
            if (d0 <= ar2) { s0 += aE; r0 += acr; g0 += acg; b0 += acb; }

            float dx1 = dx0 + dgx;
            float d1  = fmaf(dx1, dx1, dy2);
            if (d1 <= ar2) { s1 += aE; r1 += acr; g1 += acg; b1 += acb; }

            float dx2 = dx1 + dgx;
            float d2  = fmaf(dx2, dx2, dy2);
            if (d2 <= ar2) { s2 += aE; r2_ += acr; g2 += acg; b2 += acb; }

            float dx3 = dx2 + dgx;
            float d3  = fmaf(dx3, dx3, dy2);
            if (d3 <= ar2) { s3 += aE; r3 += acr; g3 += acg; b3 += acb; }
        }

        if (x0 < W_DIM) {                          // tid < 250
            float i0 = __fdividef(1.0f, s0);
            float i1 = __fdividef(1.0f, s1);
            float i2 = __fdividef(1.0f, s2);
            float i3 = __fdividef(1.0f, s3);

            float4 o0 = make_float4(r0 * i0, g0 * i0, b0 * i0, r1 * i1);
            float4 o1 = make_float4(g1 * i1, b1 * i1, r2_ * i2, g2 * i2);
            float4 o2 = make_float4(b2 * i2, r3 * i3, g3 * i3, b3 * i3);

            float4* out4 = reinterpret_cast<float4*>(out) + (size_t)row * 750 + tid * 3;
            out4[0] = o0;
            out4[1] = o1;
            out4[2] = o2;
        }
    }
}

extern "C" void kernel_launch(void* const* d_in, const int* in_sizes, int n_in,
                              void* d_out, int out_size)
{
    const float* vert_pos = (const float*)d_in[0];
    const float* vert_col = (const float*)d_in[1];
    const float* vert_rad = (const float*)d_in[2];
    const float* cam_pos  = (const float*)d_in[3];
    const float* cam_rot  = (const float*)d_in[4];
    const float* focal    = (const float*)d_in[5];
    const float* bg_col   = (const float*)d_in[6];
    float* out = (float*)d_out;

    render_kernel<<<GRID, BLOCK>>>(vert_pos, vert_col, vert_rad,
                                   cam_pos, cam_rot, focal, bg_col, out);
}

// round 9
// speedup vs baseline: 1.1630x; 1.1630x over previous
#include <cuda_runtime.h>
#include <cuda_bf16.h>
#include <math.h>

#define H_DIM 1000
#define W_DIM 1000
#define NVERT 20
#define NPIX_THREAD 4
#define BLOCK 250                      // one image row per block: 250 threads * 4 px

__global__ void __launch_bounds__(256)
render_kernel(const float* __restrict__ vpos,
              const float* __restrict__ vcol,
              const float* __restrict__ vrad,
              const float* __restrict__ cpos,
              const float* __restrict__ crot,
              const float* __restrict__ fl,
              const float* __restrict__ bg,
              float* __restrict__ out)
{
    __shared__ float4 sp[NVERT * 2];   // [xn, yn, r2, E], [E*cr, E*cg, E*cb, 0]
    __shared__ unsigned smask;

    const int t   = threadIdx.x;
    const int row = blockIdx.x;
    const float gy = 1.0f - (2.0f * row + 1.0f) * (1.0f / H_DIM);

    if (t < 32) {
        bool cover = false;
        if (t < NVERT) {
            float px = vpos[3*t+0], py = vpos[3*t+1], pz = vpos[3*t+2];
            // p_cam = vert_pos @ cam_rot + cam_pos (row-vector * row-major 3x3)
            float x = fmaf(px, crot[0], fmaf(py, crot[3], fmaf(pz, crot[6], cpos[0])));
            float y = fmaf(px, crot[1], fmaf(py, crot[4], fmaf(pz, crot[7], cpos[1])));
            float z = fmaf(px, crot[2], fmaf(py, crot[5], fmaf(pz, crot[8], cpos[2])));
            float f    = fl[0];
            float invz = __fdividef(1.0f, z);
            float xn = f * x * invz;
            float yn = f * y * invz;
            float rn = f * vrad[t] * invz;
            float r2 = rn * rn;
            bool in_depth = (z > 1.0f) && (z < 45.0f);
            float closeness = fminf(fmaxf((45.0f - z) * (1.0f / 44.0f), 0.0f), 1.0f);
            float E = in_depth ? __expf(closeness * 10.0f) : 0.0f;  // bg logit = 0 -> exp = 1
            sp[2*t]   = make_float4(xn, yn, r2, E);
            sp[2*t+1] = make_float4(E * vcol[3*t+0], E * vcol[3*t+1], E * vcol[3*t+2], 0.0f);
            float dy = gy - yn;
            cover = (dy * dy <= r2) && (E > 0.0f);
        }
        unsigned m = __ballot_sync(0xffffffffu, cover);
        if (t == 0) smask = m;
    }
    __syncthreads();

    unsigned mask = smask;

    const int x0 = t * NPIX_THREAD;
    const float dgx = -2.0f / W_DIM;
    float gx0 = 1.0f - (2.0f * x0 + 1.0f) * (1.0f / W_DIM);
    float gx1 = gx0 + dgx;
    float gx2 = gx1 + dgx;
    float gx3 = gx2 + dgx;

    const float bgr = bg[0], bgg = bg[1], bgb = bg[2];
    float s0 = 1.0f, s1 = 1.0f, s2 = 1.0f, s3 = 1.0f;  // background weight e^0 = 1
    float r0 = bgr, g0 = bgg, b0 = bgb;
    float r1 = bgr, g1 = bgg, b1 = bgb;
    float r2_ = bgr, g2 = bgg, b2 = bgb;
    float r3 = bgr, g3 = bgg, b3 = bgb;

    while (mask) {
        int i = __ffs(mask) - 1;
        mask &= mask - 1;
        float4 a = sp[2*i];       // xn, yn, r2, E
        float4 c = sp[2*i+1];     // E*cr, E*cg, E*cb
        float dy  = gy - a.y;
        float dy2 = dy * dy;

        float dx0 = gx0 - a.x;
        float d0  = fmaf(dx0, dx0, dy2);
        if (d0 <= a.z) { s0 += a.w; r0 += c.x; g0 += c.y; b0 += c.z; }

        float dx1 = gx1 - a.x;
        float d1  = fmaf(dx1, dx1, dy2);
        if (d1 <= a.z) { s1 += a.w; r1 += c.x; g1 += c.y; b1 += c.z; }

        float dx2 = gx2 - a.x;
        float d2  = fmaf(dx2, dx2, dy2);
        if (d2 <= a.z) { s2 += a.w; r2_ += c.x; g2 += c.y; b2 += c.z; }

        float dx3 = gx3 - a.x;
        float d3  = fmaf(dx3, dx3, dy2);
        if (d3 <= a.z) { s3 += a.w; r3 += c.x; g3 += c.y; b3 += c.z; }
    }

    float i0 = __fdividef(1.0f, s0);
    float i1 = __fdividef(1.0f, s1);
    float i2 = __fdividef(1.0f, s2);
    float i3 = __fdividef(1.0f, s3);

    float4 o0 = make_float4(r0 * i0, g0 * i0, b0 * i0, r1 * i1);
    float4 o1 = make_float4(g1 * i1, b1 * i1, r2_ * i2, g2 * i2);
    float4 o2 = make_float4(b2 * i2, r3 * i3, g3 * i3, b3 * i3);

    float4* out4 = reinterpret_cast<float4*>(out) + ((size_t)row * BLOCK + t) * 3;
    out4[0] = o0;
    out4[1] = o1;
    out4[2] = o2;
}

extern "C" void kernel_launch(void* const* d_in, const int* in_sizes, int n_in,
                              void* d_out, int out_size)
{
    const float* vert_pos = (const float*)d_in[0];
    const float* vert_col = (const float*)d_in[1];
    const float* vert_rad = (const float*)d_in[2];
    const float* cam_pos  = (const float*)d_in[3];
    const float* cam_rot  = (const float*)d_in[4];
    const float* focal    = (const float*)d_in[5];
    const float* bg_col   = (const float*)d_in[6];
    float* out = (float*)d_out;

    render_kernel<<<H_DIM, BLOCK>>>(vert_pos, vert_col, vert_rad,
                                    cam_pos, cam_rot, focal, bg_col, out);
}